// round 13
// baseline (speedup 1.0000x reference)
#include <cuda_runtime.h>
#include <cuda_fp16.h>
#include <math.h>
#include <stdint.h>

// MoE dims (fixed)
#define NT 16384
#define DD 512
#define HH 2048
#define EE 8
#define KK 2
#define CAP 8192
#define CROWS (CAP * EE)

// ---------------- device scratch ----------------
__device__ __half g_x16[(size_t)NT * DD];
__device__ __half g_w1t[(size_t)EE * HH * DD];   // [e][h][d] fp16
__device__ __half g_w2t[(size_t)EE * DD * HH];   // [e][d][h] fp16
__device__ __half g_h16[(size_t)CROWS * HH];
__device__ float g_y[(size_t)CROWS * DD];
__device__ int   g_perm[CROWS];
__device__ int   g_rowOf[NT * KK];
__device__ float g_gate2[NT * KK];
__device__ int   g_fill[EE];
__device__ int   g_tile1;
__device__ int   g_tile2;

__device__ __forceinline__ uint32_t smem_u32(const void* p) {
    uint32_t a;
    asm("{ .reg .u64 t; cvta.to.shared.u64 t, %1; cvt.u32.u64 %0, t; }" : "=r"(a) : "l"(p));
    return a;
}
__device__ __forceinline__ void cp16(uint32_t saddr, const void* gaddr, uint32_t sz) {
    asm volatile("cp.async.cg.shared.global [%0], [%1], 16, %2;"
                 :: "r"(saddr), "l"(gaddr), "r"(sz) : "memory");
}
#define CP_COMMIT() asm volatile("cp.async.commit_group;" ::: "memory")

__device__ __forceinline__ void ldsm_x4(uint32_t* r, uint32_t addr) {
    asm volatile("ldmatrix.sync.aligned.m8n8.x4.shared.b16 {%0,%1,%2,%3}, [%4];"
                 : "=r"(r[0]), "=r"(r[1]), "=r"(r[2]), "=r"(r[3]) : "r"(addr));
}
__device__ __forceinline__ void mma16816(float* c, const uint32_t* a, const uint32_t* b) {
    asm volatile(
        "mma.sync.aligned.m16n8k16.row.col.f32.f16.f16.f32 "
        "{%0,%1,%2,%3}, {%4,%5,%6,%7}, {%8,%9}, {%0,%1,%2,%3};"
        : "+f"(c[0]), "+f"(c[1]), "+f"(c[2]), "+f"(c[3])
        : "r"(a[0]), "r"(a[1]), "r"(a[2]), "r"(a[3]), "r"(b[0]), "r"(b[1]));
}

// ---------------- prep: zero counters + transpose W1,W2 (fp16) ----------------
__global__ __launch_bounds__(256)
void prep_kernel(const float* __restrict__ W1, const float* __restrict__ W2) {
    __shared__ float t[32][33];
    const int b = blockIdx.x;
    const int tid = threadIdx.x;

    if (b == 0 && tid < EE + 2) {
        if (tid < EE) g_fill[tid] = 0;
        else if (tid == EE) g_tile1 = 0;
        else g_tile2 = 0;
    }

    const bool isW1 = (b < 8192);
    const int  bb   = isW1 ? b : (b - 8192);
    const int  R    = isW1 ? DD : HH;
    const int  C    = isW1 ? HH : DD;
    const int  CB   = C / 32;
    const int  e    = bb / (CB * (R / 32));
    const int  rem  = bb % (CB * (R / 32));
    const int  cb   = rem % CB;
    const int  rb   = rem / CB;
    const int  c0 = cb * 32, r0 = rb * 32;
    const int  tx = tid & 31, ty = tid >> 5;

    const float* s = (isW1 ? W1 : W2) + (size_t)e * R * C;
    __half* dh = (isW1 ? g_w1t : g_w2t) + (size_t)e * R * C;

#pragma unroll
    for (int i = 0; i < 4; i++)
        t[ty + i * 8][tx] = s[(size_t)(r0 + ty + i * 8) * C + c0 + tx];
    __syncthreads();
#pragma unroll
    for (int i = 0; i < 4; i++)
        dh[(size_t)(c0 + ty + i * 8) * R + r0 + tx] = __float2half_rn(t[tx][ty + i * 8]);
}

// ---------------- router + scatter + x-convert fused ----------------
__global__ __launch_bounds__(256)
void router_kernel(const float* __restrict__ x, const float* __restrict__ Wr) {
    __shared__ float sWrT[EE * DD];
    int tid = threadIdx.x;
    for (int i = tid; i < DD * EE; i += blockDim.x) {
        int d = i / EE, e = i % EE;
        sWrT[e * DD + d] = Wr[i];
    }
    __syncthreads();
    int warp = tid >> 5, lane = tid & 31;
    int n = blockIdx.x * 8 + warp;
    if (n >= NT) return;
    float acc[EE];
#pragma unroll
    for (int e = 0; e < EE; e++) acc[e] = 0.f;
    const float* xr = x + (size_t)n * DD;
    __half* xh = g_x16 + (size_t)n * DD;
#pragma unroll
    for (int it = 0; it < DD / 32; it++) {
        float xv = xr[lane + it * 32];
        xh[lane + it * 32] = __float2half_rn(xv);
#pragma unroll
        for (int e = 0; e < EE; e++) acc[e] += xv * sWrT[e * DD + lane + it * 32];
    }
#pragma unroll
    for (int e = 0; e < EE; e++)
#pragma unroll
        for (int s = 16; s > 0; s >>= 1)
            acc[e] += __shfl_xor_sync(0xffffffffu, acc[e], s);
    if (lane == 0) {
        float m = acc[0];
#pragma unroll
        for (int e = 1; e < EE; e++) m = fmaxf(m, acc[e]);
        float p[EE], s = 0.f;
#pragma unroll
        for (int e = 0; e < EE; e++) { p[e] = expf(acc[e] - m); s += p[e]; }
        float inv = 1.f / s;
        int i1 = 0; float v1 = p[0];
#pragma unroll
        for (int e = 1; e < EE; e++) if (p[e] > v1) { v1 = p[e]; i1 = e; }
        int i2 = -1; float v2 = -1.f;
#pragma unroll
        for (int e = 0; e < EE; e++) if (e != i1 && p[e] > v2) { v2 = p[e]; i2 = e; }
        int pos1 = atomicAdd(&g_fill[i1], 1);
        int row1 = i1 * CAP + pos1;
        g_perm[row1] = n;
        g_rowOf[2 * n + 0] = row1;
        g_gate2[2 * n + 0] = v1 * inv;
        int pos2 = atomicAdd(&g_fill[i2], 1);
        int row2 = i2 * CAP + pos2;
        g_perm[row2] = n;
        g_rowOf[2 * n + 1] = row2;
        g_gate2[2 * n + 1] = v2 * inv;
    }
}

// ---------------- persistent HMMA GEMM, continuous cross-tile cp.async ring ----------
#define ROWB 80
#define ARR_BYTES (128 * ROWB)          // 10240
#define STAGE_BYTES (2 * ARR_BYTES)     // 20480
#define NSTAGE 5
#define SMEM_GEMM_BYTES (NSTAGE * STAGE_BYTES + 128)
#define NPERSIST 296

template <bool FC1>
__global__ __launch_bounds__(256, 2)
void moe_gemm_hmma_kernel(const float* __restrict__ bias) {
    constexpr int Kd = FC1 ? DD : HH;
    constexpr int Nd = FC1 ? HH : DD;
    constexpr int NCHUNK = Kd / 32;
    constexpr int NTILES = Nd / 128;

    extern __shared__ char smem[];
    int* stile = (int*)(smem + NSTAGE * STAGE_BYTES);   // [0],[1] ping-pong
    int* sfill = stile + 2;                              // [8] expert counts
    const int tid = threadIdx.x;
    const int wid = tid >> 5, lane = tid & 31;

    const __half* aP = FC1 ? g_x16 : g_h16;
    const __half* wB = FC1 ? g_w1t : g_w2t;
    int* ctr = FC1 ? &g_tile1 : &g_tile2;

    if (tid < EE) sfill[tid] = g_fill[tid];
    if (tid == 0) stile[0] = atomicAdd(ctr, 1);
    __syncthreads();

    int total = 0;
#pragma unroll
    for (int e = 0; e < EE; e++)
        total += ((sfill[e] + 127) >> 7) * NTILES;

    const int srow = tid >> 1;
    const int part = tid & 1;
    const uint32_t sb = smem_u32(smem);
    const uint32_t rowoff = srow * ROWB + part * 32;

    const int warpM = (wid >> 1) * 32;
    const int warpN = (wid & 1) * 64;
    const int g = lane >> 3, lr = lane & 7;
    const uint32_t aLaneOff = (uint32_t)(warpM + lr + ((g & 1) << 3)) * ROWB + ((g >> 1) << 4);
    const uint32_t bLaneOff = (uint32_t)(warpN + lr + ((g >> 1) << 3)) * ROWB + ((g & 1) << 4);
    const int rr = lane >> 2;
    const int cc2 = (lane & 3) * 2;

    auto decode = [&](int t, int& e, int& cnt, int& m0, int& n0) {
        int rem = t; e = 0;
#pragma unroll 1
        for (; e < EE - 1; e++) {
            int te = ((sfill[e] + 127) >> 7) * NTILES;
            if (rem < te) break;
            rem -= te;
        }
        cnt = sfill[e];
        m0 = (rem / NTILES) * 128;
        n0 = (rem % NTILES) * 128;
    };

    int t_stage = stile[0];
    bool s_valid = (t_stage < total);
    const __half* s_pah = aP;
    const __half* s_pbh = wB;
    uint32_t s_aok = 0;

    auto decodeS = [&]() {
        int e, cnt, m0, n0;
        decode(t_stage, e, cnt, m0, n0);
        int m = m0 + srow;
        long long arow = -1;
        if (m < cnt) arow = FC1 ? (long long)g_perm[e * CAP + m] * DD
                                : (long long)(e * CAP + m) * HH;
        s_aok = (arow >= 0) ? 16u : 0u;
        s_pah = aP + (arow >= 0 ? arow : 0);
        s_pbh = wB + ((size_t)e * Nd + n0 + srow) * Kd;
    };

    auto stage = [&](int slot, int kchunk) {
        if (s_valid) {
            const uint32_t so = (uint32_t)slot * STAGE_BYTES + rowoff;
            const int k0 = kchunk * 32 + part * 16;
#pragma unroll
            for (int i = 0; i < 2; i++) {
                int ke = k0 + i * 8;
                cp16(sb + so             + i * 16, s_pah + ke, s_aok);
                cp16(sb + so + ARR_BYTES + i * 16, s_pbh + ke, 16u);
            }
        }
        CP_COMMIT();
    };

    if (s_valid) decodeS();
    if (tid == 0) stile[1] = atomicAdd(ctr, 1);
    int pp = 1;

    stage(0, 0); stage(1, 1); stage(2, 2); stage(3, 3);

    int t_cur = t_stage;
    bool c_valid = s_valid;
    int cslot = 0;

    float acc[2][8][4];
#pragma unroll
    for (int i = 0; i < 2; i++)
#pragma unroll
        for (int j = 0; j < 8; j++)
#pragma unroll
            for (int k = 0; k < 4; k++) acc[i][j][k] = 0.f;

#pragma unroll 1
    while (c_valid) {
#pragma unroll 1
        for (int c = 0; c < NCHUNK; c++) {
            asm volatile("cp.async.wait_group 3;" ::: "memory");
            __syncthreads();

            if (c == NCHUNK - 4) {
                t_stage = stile[pp];
                s_valid = (t_stage < total);
                if (s_valid) decodeS();
                if (tid == 0) stile[pp ^ 1] = atomicAdd(ctr, 1);
                pp ^= 1;
            }
            int ss = cslot + 4; if (ss >= NSTAGE) ss -= NSTAGE;
            int kc = c + 4;     if (kc >= NCHUNK) kc -= NCHUNK;
            stage(ss, kc);

            const uint32_t st = (uint32_t)cslot * STAGE_BYTES;
            const uint32_t sA = sb + st;
            const uint32_t sB = sA + ARR_BYTES;
#pragma unroll
            for (int ks = 0; ks < 2; ks++) {
                const uint32_t ko = ks * 32;
                uint32_t bh[16];
#pragma unroll
                for (int tt = 0; tt < 4; tt++)
                    ldsm_x4(bh + 4 * tt, sB + ko + bLaneOff + tt * 16 * ROWB);
                uint32_t ah[8];
#pragma unroll
                for (int mt = 0; mt < 2; mt++)
                    ldsm_x4(ah + 4 * mt, sA + ko + aLaneOff + mt * 16 * ROWB);
#pragma unroll
                for (int mt = 0; mt < 2; mt++) {
#pragma unroll
                    for (int nf = 0; nf < 8; nf++) {
                        const uint32_t* B = &bh[4 * (nf >> 1) + 2 * (nf & 1)];
                        mma16816(acc[mt][nf], ah + 4 * mt, B);
                    }
                }
            }
            if (++cslot == NSTAGE) cslot = 0;
        }

        // epilogue for t_cur — overlaps with in-flight staging of next tile
        {
            int e, cnt, m0, n0;
            decode(t_cur, e, cnt, m0, n0);
            const int off = e * CAP;
#pragma unroll
            for (int mt = 0; mt < 2; mt++) {
#pragma unroll
                for (int nf = 0; nf < 8; nf++) {
                    int col = n0 + warpN + nf * 8 + cc2;
                    float bv0 = __ldg(&bias[(size_t)e * Nd + col]);
                    float bv1 = __ldg(&bias[(size_t)e * Nd + col + 1]);
#pragma unroll
                    for (int h = 0; h < 2; h++) {
                        int m = m0 + warpM + mt * 16 + rr + h * 8;
                        if (m < cnt) {
                            float v0 = acc[mt][nf][h * 2 + 0] + bv0;
                            float v1 = acc[mt][nf][h * 2 + 1] + bv1;
                            size_t orow = (size_t)(off + m);
                            if (FC1) {
                                v0 = fmaxf(v0, 0.f); v1 = fmaxf(v1, 0.f);
                                *(__half2*)(g_h16 + orow * HH + col) =
                                    __halves2half2(__float2half_rn(v0), __float2half_rn(v1));
                            } else {
                                *(float2*)(g_y + orow * DD + col) = make_float2(v0, v1);
                            }
                        }
                    }
                }
            }
        }
#pragma unroll
        for (int i = 0; i < 2; i++)
#pragma unroll
            for (int j = 0; j < 8; j++)
#pragma unroll
                for (int k = 0; k < 4; k++) acc[i][j][k] = 0.f;
        t_cur = t_stage;
        c_valid = s_valid;
    }
}

// ---------------- combine ----------------
__global__ __launch_bounds__(128)
void combine_kernel(float* __restrict__ out) {
    int n = blockIdx.x;
    int d = threadIdx.x * 4;
    int r0 = g_rowOf[2 * n + 0];
    int r1 = g_rowOf[2 * n + 1];
    float g0 = g_gate2[2 * n + 0];
    float g1 = g_gate2[2 * n + 1];
    float4 y0 = *(const float4*)&g_y[(size_t)r0 * DD + d];
    float4 y1 = *(const float4*)&g_y[(size_t)r1 * DD + d];
    float4 o;
    o.x = g0 * y0.x + g1 * y1.x;
    o.y = g0 * y0.y + g1 * y1.y;
    o.z = g0 * y0.z + g1 * y1.z;
    o.w = g0 * y0.w + g1 * y1.w;
    *(float4*)&out[(size_t)n * DD + d] = o;
}

__global__ void tail_kernel(float* __restrict__ out, long long start, long long total) {
    long long i = start + (long long)blockIdx.x * blockDim.x + threadIdx.x;
    if (i < total) out[i] = 0.f;
}

extern "C" void kernel_launch(void* const* d_in, const int* in_sizes, int n_in,
                              void* d_out, int out_size) {
    const float* x  = (const float*)d_in[0];
    const float* Wr = (const float*)d_in[1];
    const float* W1 = (const float*)d_in[2];
    const float* b1 = (const float*)d_in[3];
    const float* W2 = (const float*)d_in[4];
    const float* b2 = (const float*)d_in[5];
    float* out = (float*)d_out;

    cudaFuncSetAttribute(moe_gemm_hmma_kernel<true>,
                         cudaFuncAttributeMaxDynamicSharedMemorySize, SMEM_GEMM_BYTES);
    cudaFuncSetAttribute(moe_gemm_hmma_kernel<false>,
                         cudaFuncAttributeMaxDynamicSharedMemorySize, SMEM_GEMM_BYTES);

    prep_kernel<<<16384, 256>>>(W1, W2);
    router_kernel<<<NT / 8, 256>>>(x, Wr);
    moe_gemm_hmma_kernel<true ><<<NPERSIST, 256, SMEM_GEMM_BYTES>>>(b1);
    moe_gemm_hmma_kernel<false><<<NPERSIST, 256, SMEM_GEMM_BYTES>>>(b2);
    combine_kernel<<<NT, 128>>>(out);

    long long main_elems = (long long)NT * DD;
    long long total = (long long)out_size;
    if (total > main_elems) {
        long long tail = total - main_elems;
        int blocks = (int)((tail + 255) / 256);
        tail_kernel<<<blocks, 256>>>(out, main_elems, total);
    }
}

// round 14
// speedup vs baseline: 1.0307x; 1.0307x over previous
#include <cuda_runtime.h>
#include <cuda_fp16.h>
#include <math.h>
#include <stdint.h>

// MoE dims (fixed)
#define NT 16384
#define DD 512
#define HH 2048
#define EE 8
#define KK 2
#define CAP 8192
#define CROWS (CAP * EE)

// ---------------- device scratch ----------------
__device__ __half g_x16[(size_t)NT * DD];
__device__ __half g_w1t[(size_t)EE * HH * DD];   // [e][h][d] fp16
__device__ __half g_w2t[(size_t)EE * DD * HH];   // [e][d][h] fp16
__device__ __half g_h16[(size_t)CROWS * HH];
__device__ float g_y[(size_t)CROWS * DD];
__device__ int   g_perm[CROWS];
__device__ int   g_rowOf[NT * KK];
__device__ float g_gate2[NT * KK];
__device__ int   g_fill[EE];
__device__ int   g_tile1;
__device__ int   g_tile2;

__device__ __forceinline__ uint32_t smem_u32(const void* p) {
    uint32_t a;
    asm("{ .reg .u64 t; cvta.to.shared.u64 t, %1; cvt.u32.u64 %0, t; }" : "=r"(a) : "l"(p));
    return a;
}
__device__ __forceinline__ void cp16(uint32_t saddr, const void* gaddr, uint32_t sz) {
    asm volatile("cp.async.cg.shared.global [%0], [%1], 16, %2;"
                 :: "r"(saddr), "l"(gaddr), "r"(sz) : "memory");
}
#define CP_COMMIT() asm volatile("cp.async.commit_group;" ::: "memory")

__device__ __forceinline__ void ldsm_x4(uint32_t* r, uint32_t addr) {
    asm volatile("ldmatrix.sync.aligned.m8n8.x4.shared.b16 {%0,%1,%2,%3}, [%4];"
                 : "=r"(r[0]), "=r"(r[1]), "=r"(r[2]), "=r"(r[3]) : "r"(addr));
}
__device__ __forceinline__ void mma16816(float* c, const uint32_t* a, const uint32_t* b) {
    asm volatile(
        "mma.sync.aligned.m16n8k16.row.col.f32.f16.f16.f32 "
        "{%0,%1,%2,%3}, {%4,%5,%6,%7}, {%8,%9}, {%0,%1,%2,%3};"
        : "+f"(c[0]), "+f"(c[1]), "+f"(c[2]), "+f"(c[3])
        : "r"(a[0]), "r"(a[1]), "r"(a[2]), "r"(a[3]), "r"(b[0]), "r"(b[1]));
}

// ---------------- prep: zero counters + transpose W1,W2 (fp16) ----------------
__global__ __launch_bounds__(256)
void prep_kernel(const float* __restrict__ W1, const float* __restrict__ W2) {
    __shared__ float t[32][33];
    const int b = blockIdx.x;
    const int tid = threadIdx.x;

    if (b == 0 && tid < EE + 2) {
        if (tid < EE) g_fill[tid] = 0;
        else if (tid == EE) g_tile1 = 0;
        else g_tile2 = 0;
    }

    const bool isW1 = (b < 8192);
    const int  bb   = isW1 ? b : (b - 8192);
    const int  R    = isW1 ? DD : HH;
    const int  C    = isW1 ? HH : DD;
    const int  CB   = C / 32;
    const int  e    = bb / (CB * (R / 32));
    const int  rem  = bb % (CB * (R / 32));
    const int  cb   = rem % CB;
    const int  rb   = rem / CB;
    const int  c0 = cb * 32, r0 = rb * 32;
    const int  tx = tid & 31, ty = tid >> 5;

    const float* s = (isW1 ? W1 : W2) + (size_t)e * R * C;
    __half* dh = (isW1 ? g_w1t : g_w2t) + (size_t)e * R * C;

#pragma unroll
    for (int i = 0; i < 4; i++)
        t[ty + i * 8][tx] = s[(size_t)(r0 + ty + i * 8) * C + c0 + tx];
    __syncthreads();
#pragma unroll
    for (int i = 0; i < 4; i++)
        dh[(size_t)(c0 + ty + i * 8) * R + r0 + tx] = __float2half_rn(t[tx][ty + i * 8]);
}

// ---------------- router + scatter + x-convert fused ----------------
__global__ __launch_bounds__(256)
void router_kernel(const float* __restrict__ x, const float* __restrict__ Wr) {
    __shared__ float sWrT[EE * DD];
    int tid = threadIdx.x;
    for (int i = tid; i < DD * EE; i += blockDim.x) {
        int d = i / EE, e = i % EE;
        sWrT[e * DD + d] = Wr[i];
    }
    __syncthreads();
    int warp = tid >> 5, lane = tid & 31;
    int n = blockIdx.x * 8 + warp;
    if (n >= NT) return;
    float acc[EE];
#pragma unroll
    for (int e = 0; e < EE; e++) acc[e] = 0.f;
    const float* xr = x + (size_t)n * DD;
    __half* xh = g_x16 + (size_t)n * DD;
#pragma unroll
    for (int it = 0; it < DD / 32; it++) {
        float xv = xr[lane + it * 32];
        xh[lane + it * 32] = __float2half_rn(xv);
#pragma unroll
        for (int e = 0; e < EE; e++) acc[e] += xv * sWrT[e * DD + lane + it * 32];
    }
#pragma unroll
    for (int e = 0; e < EE; e++)
#pragma unroll
        for (int s = 16; s > 0; s >>= 1)
            acc[e] += __shfl_xor_sync(0xffffffffu, acc[e], s);
    if (lane == 0) {
        float m = acc[0];
#pragma unroll
        for (int e = 1; e < EE; e++) m = fmaxf(m, acc[e]);
        float p[EE], s = 0.f;
#pragma unroll
        for (int e = 0; e < EE; e++) { p[e] = expf(acc[e] - m); s += p[e]; }
        float inv = 1.f / s;
        int i1 = 0; float v1 = p[0];
#pragma unroll
        for (int e = 1; e < EE; e++) if (p[e] > v1) { v1 = p[e]; i1 = e; }
        int i2 = -1; float v2 = -1.f;
#pragma unroll
        for (int e = 0; e < EE; e++) if (e != i1 && p[e] > v2) { v2 = p[e]; i2 = e; }
        int pos1 = atomicAdd(&g_fill[i1], 1);
        int row1 = i1 * CAP + pos1;
        g_perm[row1] = n;
        g_rowOf[2 * n + 0] = row1;
        g_gate2[2 * n + 0] = v1 * inv;
        int pos2 = atomicAdd(&g_fill[i2], 1);
        int row2 = i2 * CAP + pos2;
        g_perm[row2] = n;
        g_rowOf[2 * n + 1] = row2;
        g_gate2[2 * n + 1] = v2 * inv;
    }
}

// ---------------- persistent HMMA GEMM (R12 hot loop + boundary refill overlap) ------
#define ROWB 80
#define ARR_BYTES (128 * ROWB)          // 10240
#define STAGE_BYTES (2 * ARR_BYTES)     // 20480
#define NSTAGE 5
#define SMEM_GEMM_BYTES (NSTAGE * STAGE_BYTES + 128)
#define NPERSIST 296

template <bool FC1>
__global__ __launch_bounds__(256, 2)
void moe_gemm_hmma_kernel(const float* __restrict__ bias) {
    constexpr int Kd = FC1 ? DD : HH;
    constexpr int Nd = FC1 ? HH : DD;
    constexpr int NCHUNK = Kd / 32;
    constexpr int NTILES = Nd / 128;

    extern __shared__ char smem[];
    int* stile = (int*)(smem + NSTAGE * STAGE_BYTES);   // [0],[1] ping-pong
    int* sfill = stile + 2;                              // [8] expert counts
    const int tid = threadIdx.x;
    const int wid = tid >> 5, lane = tid & 31;

    const __half* aP = FC1 ? g_x16 : g_h16;
    const __half* wB = FC1 ? g_w1t : g_w2t;
    int* ctr = FC1 ? &g_tile1 : &g_tile2;

    if (tid < EE) sfill[tid] = g_fill[tid];
    if (tid == 0) stile[0] = atomicAdd(ctr, 1);
    __syncthreads();

    int total = 0;
#pragma unroll
    for (int e = 0; e < EE; e++)
        total += ((sfill[e] + 127) >> 7) * NTILES;

    const int srow = tid >> 1;
    const int part = tid & 1;
    const uint32_t sb = smem_u32(smem);
    const uint32_t rowoff = srow * ROWB + part * 32;

    const int warpM = (wid >> 1) * 32;
    const int warpN = (wid & 1) * 64;
    const int g = lane >> 3, lr = lane & 7;
    const uint32_t aLaneOff = (uint32_t)(warpM + lr + ((g & 1) << 3)) * ROWB + ((g >> 1) << 4);
    const uint32_t bLaneOff = (uint32_t)(warpN + lr + ((g >> 1) << 3)) * ROWB + ((g & 1) << 4);
    const int rr = lane >> 2;
    const int cc2 = (lane & 3) * 2;

    auto decode = [&](int t, int& e, int& cnt, int& m0, int& n0) {
        int rem = t; e = 0;
#pragma unroll 1
        for (; e < EE - 1; e++) {
            int te = ((sfill[e] + 127) >> 7) * NTILES;
            if (rem < te) break;
            rem -= te;
        }
        cnt = sfill[e];
        m0 = (rem / NTILES) * 128;
        n0 = (rem % NTILES) * 128;
    };

    // compute per-thread staging pointers for a tile
    auto mkptrs = [&](int e, int cnt, int m0, int n0,
                      const __half*& pah, const __half*& pbh, uint32_t& aok) {
        int m = m0 + srow;
        long long arow = -1;
        if (m < cnt) arow = FC1 ? (long long)g_perm[e * CAP + m] * DD
                                : (long long)(e * CAP + m) * HH;
        aok = (arow >= 0) ? 16u : 0u;
        pah = aP + (arow >= 0 ? arow : 0);
        pbh = wB + ((size_t)e * Nd + n0 + srow) * Kd;
    };

    auto stage = [&](const __half* pah, const __half* pbh, uint32_t aok, int c) {
        const uint32_t so = (uint32_t)(c % NSTAGE) * STAGE_BYTES + rowoff;
        const int k0 = c * 32 + part * 16;
#pragma unroll
        for (int i = 0; i < 2; i++) {
            int ke = k0 + i * 8;
            cp16(sb + so             + i * 16, pah + ke, aok);
            cp16(sb + so + ARR_BYTES + i * 16, pbh + ke, 16u);
        }
        CP_COMMIT();
    };

    // current tile state
    int t_cur = stile[0];
    if (t_cur >= total) return;
    int ce, ccnt, cm0, cn0;
    decode(t_cur, ce, ccnt, cm0, cn0);
    const __half *c_pah, *c_pbh; uint32_t c_aok;
    mkptrs(ce, ccnt, cm0, cn0, c_pah, c_pbh, c_aok);

    if (tid == 0) stile[1] = atomicAdd(ctr, 1);
    int pp = 1;

    // prologue refill
    stage(c_pah, c_pbh, c_aok, 0);
    stage(c_pah, c_pbh, c_aok, 1);
    stage(c_pah, c_pbh, c_aok, 2);
    stage(c_pah, c_pbh, c_aok, 3);

    float acc[2][8][4];
#pragma unroll
    for (int i = 0; i < 2; i++)
#pragma unroll
        for (int j = 0; j < 8; j++)
#pragma unroll
            for (int k = 0; k < 4; k++) acc[i][j][k] = 0.f;

#pragma unroll 1
    while (true) {
        // ------- hot loop: IDENTICAL to R12 -------
#pragma unroll 1
        for (int c = 0; c < NCHUNK; c++) {
            if (c + 3 < NCHUNK)      asm volatile("cp.async.wait_group 3;" ::: "memory");
            else if (c + 2 < NCHUNK) asm volatile("cp.async.wait_group 2;" ::: "memory");
            else if (c + 1 < NCHUNK) asm volatile("cp.async.wait_group 1;" ::: "memory");
            else                     asm volatile("cp.async.wait_group 0;" ::: "memory");
            __syncthreads();
            if (c + 4 < NCHUNK) stage(c_pah, c_pbh, c_aok, c + 4);

            const uint32_t st = (uint32_t)(c % NSTAGE) * STAGE_BYTES;
            const uint32_t sA = sb + st;
            const uint32_t sB = sA + ARR_BYTES;
#pragma unroll
            for (int ks = 0; ks < 2; ks++) {
                const uint32_t ko = ks * 32;
                uint32_t bh[16];
#pragma unroll
                for (int tt = 0; tt < 4; tt++)
                    ldsm_x4(bh + 4 * tt, sB + ko + bLaneOff + tt * 16 * ROWB);
                uint32_t ah[8];
#pragma unroll
                for (int mt = 0; mt < 2; mt++)
                    ldsm_x4(ah + 4 * mt, sA + ko + aLaneOff + mt * 16 * ROWB);
#pragma unroll
                for (int mt = 0; mt < 2; mt++) {
#pragma unroll
                    for (int nf = 0; nf < 8; nf++) {
                        const uint32_t* B = &bh[4 * (nf >> 1) + 2 * (nf & 1)];
                        mma16816(acc[mt][nf], ah + 4 * mt, B);
                    }
                }
            }
        }

        // ------- boundary: refill next tile BEFORE epilogue -------
        __syncthreads();   // all slots drained and no warp still reads smem
        int t_next = stile[pp];
        bool v_next = (t_next < total);
        int ne = 0, ncnt = 0, nm0 = 0, nn0 = 0;
        const __half *n_pah = aP, *n_pbh = wB; uint32_t n_aok = 0;
        if (v_next) {
            decode(t_next, ne, ncnt, nm0, nn0);
            mkptrs(ne, ncnt, nm0, nn0, n_pah, n_pbh, n_aok);
            stage(n_pah, n_pbh, n_aok, 0);
            stage(n_pah, n_pbh, n_aok, 1);
            stage(n_pah, n_pbh, n_aok, 2);
            stage(n_pah, n_pbh, n_aok, 3);
        }
        if (tid == 0) stile[pp ^ 1] = atomicAdd(ctr, 1);
        pp ^= 1;

        // ------- epilogue for current tile (overlaps next tile's loads) -------
        {
            const int off = ce * CAP;
#pragma unroll
            for (int mt = 0; mt < 2; mt++) {
#pragma unroll
                for (int nf = 0; nf < 8; nf++) {
                    int col = cn0 + warpN + nf * 8 + cc2;
                    float bv0 = __ldg(&bias[(size_t)ce * Nd + col]);
                    float bv1 = __ldg(&bias[(size_t)ce * Nd + col + 1]);
#pragma unroll
                    for (int h = 0; h < 2; h++) {
                        int m = cm0 + warpM + mt * 16 + rr + h * 8;
                        if (m < ccnt) {
                            float v0 = acc[mt][nf][h * 2 + 0] + bv0;
                            float v1 = acc[mt][nf][h * 2 + 1] + bv1;
                            size_t orow = (size_t)(off + m);
                            if (FC1) {
                                v0 = fmaxf(v0, 0.f); v1 = fmaxf(v1, 0.f);
                                *(__half2*)(g_h16 + orow * HH + col) =
                                    __halves2half2(__float2half_rn(v0), __float2half_rn(v1));
                            } else {
                                *(float2*)(g_y + orow * DD + col) = make_float2(v0, v1);
                            }
                        }
                    }
                }
            }
        }
#pragma unroll
        for (int i = 0; i < 2; i++)
#pragma unroll
            for (int j = 0; j < 8; j++)
#pragma unroll
                for (int k = 0; k < 4; k++) acc[i][j][k] = 0.f;

        if (!v_next) break;
        ce = ne; ccnt = ncnt; cm0 = nm0; cn0 = nn0;
        c_pah = n_pah; c_pbh = n_pbh; c_aok = n_aok;
    }
}

// ---------------- combine ----------------
__global__ __launch_bounds__(128)
void combine_kernel(float* __restrict__ out) {
    int n = blockIdx.x;
    int d = threadIdx.x * 4;
    int r0 = g_rowOf[2 * n + 0];
    int r1 = g_rowOf[2 * n + 1];
    float g0 = g_gate2[2 * n + 0];
    float g1 = g_gate2[2 * n + 1];
    float4 y0 = *(const float4*)&g_y[(size_t)r0 * DD + d];
    float4 y1 = *(const float4*)&g_y[(size_t)r1 * DD + d];
    float4 o;
    o.x = g0 * y0.x + g1 * y1.x;
    o.y = g0 * y0.y + g1 * y1.y;
    o.z = g0 * y0.z + g1 * y1.z;
    o.w = g0 * y0.w + g1 * y1.w;
    *(float4*)&out[(size_t)n * DD + d] = o;
}

__global__ void tail_kernel(float* __restrict__ out, long long start, long long total) {
    long long i = start + (long long)blockIdx.x * blockDim.x + threadIdx.x;
    if (i < total) out[i] = 0.f;
}

extern "C" void kernel_launch(void* const* d_in, const int* in_sizes, int n_in,
                              void* d_out, int out_size) {
    const float* x  = (const float*)d_in[0];
    const float* Wr = (const float*)d_in[1];
    const float* W1 = (const float*)d_in[2];
    const float* b1 = (const float*)d_in[3];
    const float* W2 = (const float*)d_in[4];
    const float* b2 = (const float*)d_in[5];
    float* out = (float*)d_out;

    cudaFuncSetAttribute(moe_gemm_hmma_kernel<true>,
                         cudaFuncAttributeMaxDynamicSharedMemorySize, SMEM_GEMM_BYTES);
    cudaFuncSetAttribute(moe_gemm_hmma_kernel<false>,
                         cudaFuncAttributeMaxDynamicSharedMemorySize, SMEM_GEMM_BYTES);

    prep_kernel<<<16384, 256>>>(W1, W2);
    router_kernel<<<NT / 8, 256>>>(x, Wr);
    moe_gemm_hmma_kernel<true ><<<NPERSIST, 256, SMEM_GEMM_BYTES>>>(b1);
    moe_gemm_hmma_kernel<false><<<NPERSIST, 256, SMEM_GEMM_BYTES>>>(b2);
    combine_kernel<<<NT, 128>>>(out);

    long long main_elems = (long long)NT * DD;
    long long total = (long long)out_size;
    if (total > main_elems) {
        long long tail = total - main_elems;
        int blocks = (int)((tail + 255) / 256);
        tail_kernel<<<blocks, 256>>>(out, main_elems, total);
    }
}

// round 15
// speedup vs baseline: 1.0370x; 1.0061x over previous
#include <cuda_runtime.h>
#include <cuda_fp16.h>
#include <math.h>
#include <stdint.h>

// MoE dims (fixed)
#define NT 16384
#define DD 512
#define HH 2048
#define EE 8
#define KK 2
#define CAP 8192
#define CROWS (CAP * EE)

// ---------------- device scratch ----------------
__device__ __half g_x16[(size_t)NT * DD];
__device__ __half g_w1t[(size_t)EE * HH * DD];   // [e][h][d] fp16
__device__ __half g_w2t[(size_t)EE * DD * HH];   // [e][d][h] fp16
__device__ __half g_h16[(size_t)CROWS * HH];
__device__ float g_y[(size_t)CROWS * DD];
__device__ int   g_perm[CROWS];
__device__ int   g_rowOf[NT * KK];
__device__ float g_gate2[NT * KK];
__device__ int   g_fill[EE];
__device__ int   g_tile1;
__device__ int   g_tile2;

__device__ __forceinline__ uint32_t smem_u32(const void* p) {
    uint32_t a;
    asm("{ .reg .u64 t; cvta.to.shared.u64 t, %1; cvt.u32.u64 %0, t; }" : "=r"(a) : "l"(p));
    return a;
}
__device__ __forceinline__ void cp16(uint32_t saddr, const void* gaddr, uint32_t sz) {
    asm volatile("cp.async.cg.shared.global [%0], [%1], 16, %2;"
                 :: "r"(saddr), "l"(gaddr), "r"(sz) : "memory");
}
#define CP_COMMIT() asm volatile("cp.async.commit_group;" ::: "memory")

__device__ __forceinline__ void ldsm_x4(uint32_t* r, uint32_t addr) {
    asm volatile("ldmatrix.sync.aligned.m8n8.x4.shared.b16 {%0,%1,%2,%3}, [%4];"
                 : "=r"(r[0]), "=r"(r[1]), "=r"(r[2]), "=r"(r[3]) : "r"(addr));
}
__device__ __forceinline__ void mma16816(float* c, const uint32_t* a, const uint32_t* b) {
    asm volatile(
        "mma.sync.aligned.m16n8k16.row.col.f32.f16.f16.f32 "
        "{%0,%1,%2,%3}, {%4,%5,%6,%7}, {%8,%9}, {%0,%1,%2,%3};"
        : "+f"(c[0]), "+f"(c[1]), "+f"(c[2]), "+f"(c[3])
        : "r"(a[0]), "r"(a[1]), "r"(a[2]), "r"(a[3]), "r"(b[0]), "r"(b[1]));
}

// ---------------- setup: W transpose + router + x-convert + counter zero, ONE launch ----
// blocks [0,8192): W1 transpose   [8192,16384): W2 transpose   [16384,18432): router
#define NB_W  16384
#define NB_R  (NT / 8)
#define NB_SETUP (NB_W + NB_R)

__global__ __launch_bounds__(256)
void setup_kernel(const float* __restrict__ x, const float* __restrict__ Wr,
                  const float* __restrict__ W1, const float* __restrict__ W2) {
    __shared__ float sh[EE * DD];   // router: WrT (16 KB); transpose: uses first 32*33
    const int b = blockIdx.x;
    const int tid = threadIdx.x;

    if (b < NB_W) {
        // ---- weight transpose+convert ----
        if (b == 0 && tid < EE + 2) {
            if (tid < EE) g_fill[tid] = 0;
            else if (tid == EE) g_tile1 = 0;
            else g_tile2 = 0;
        }
        float (*t)[33] = (float(*)[33])sh;
        const bool isW1 = (b < 8192);
        const int  bb   = isW1 ? b : (b - 8192);
        const int  R    = isW1 ? DD : HH;
        const int  C    = isW1 ? HH : DD;
        const int  CB   = C / 32;
        const int  e    = bb / (CB * (R / 32));
        const int  rem  = bb % (CB * (R / 32));
        const int  cb   = rem % CB;
        const int  rb   = rem / CB;
        const int  c0 = cb * 32, r0 = rb * 32;
        const int  tx = tid & 31, ty = tid >> 5;

        const float* s = (isW1 ? W1 : W2) + (size_t)e * R * C;
        __half* dh = (isW1 ? g_w1t : g_w2t) + (size_t)e * R * C;

#pragma unroll
        for (int i = 0; i < 4; i++)
            t[ty + i * 8][tx] = s[(size_t)(r0 + ty + i * 8) * C + c0 + tx];
        __syncthreads();
#pragma unroll
        for (int i = 0; i < 4; i++)
            dh[(size_t)(c0 + ty + i * 8) * R + r0 + tx] = __float2half_rn(t[tx][ty + i * 8]);
        return;
    }

    // ---- router + scatter + x-convert ----
    const int rb = b - NB_W;
    for (int i = tid; i < DD * EE; i += blockDim.x) {
        int d = i / EE, e = i % EE;
        sh[e * DD + d] = Wr[i];
    }
    __syncthreads();
    int warp = tid >> 5, lane = tid & 31;
    int n = rb * 8 + warp;
    if (n >= NT) return;
    float acc[EE];
#pragma unroll
    for (int e = 0; e < EE; e++) acc[e] = 0.f;
    const float* xr = x + (size_t)n * DD;
    __half* xh = g_x16 + (size_t)n * DD;
#pragma unroll
    for (int it = 0; it < DD / 32; it++) {
        float xv = xr[lane + it * 32];
        xh[lane + it * 32] = __float2half_rn(xv);
#pragma unroll
        for (int e = 0; e < EE; e++) acc[e] += xv * sh[e * DD + lane + it * 32];
    }
#pragma unroll
    for (int e = 0; e < EE; e++)
#pragma unroll
        for (int s = 16; s > 0; s >>= 1)
            acc[e] += __shfl_xor_sync(0xffffffffu, acc[e], s);
    if (lane == 0) {
        float m = acc[0];
#pragma unroll
        for (int e = 1; e < EE; e++) m = fmaxf(m, acc[e]);
        float p[EE], s = 0.f;
#pragma unroll
        for (int e = 0; e < EE; e++) { p[e] = expf(acc[e] - m); s += p[e]; }
        float inv = 1.f / s;
        int i1 = 0; float v1 = p[0];
#pragma unroll
        for (int e = 1; e < EE; e++) if (p[e] > v1) { v1 = p[e]; i1 = e; }
        int i2 = -1; float v2 = -1.f;
#pragma unroll
        for (int e = 0; e < EE; e++) if (e != i1 && p[e] > v2) { v2 = p[e]; i2 = e; }
        int pos1 = atomicAdd(&g_fill[i1], 1);
        int row1 = i1 * CAP + pos1;
        g_perm[row1] = n;
        g_rowOf[2 * n + 0] = row1;
        g_gate2[2 * n + 0] = v1 * inv;
        int pos2 = atomicAdd(&g_fill[i2], 1);
        int row2 = i2 * CAP + pos2;
        g_perm[row2] = n;
        g_rowOf[2 * n + 1] = row2;
        g_gate2[2 * n + 1] = v2 * inv;
    }
}

// ---------------- persistent HMMA GEMM (R14, unchanged) ----------------
#define ROWB 80
#define ARR_BYTES (128 * ROWB)          // 10240
#define STAGE_BYTES (2 * ARR_BYTES)     // 20480
#define NSTAGE 5
#define SMEM_GEMM_BYTES (NSTAGE * STAGE_BYTES + 128)
#define NPERSIST 296

template <bool FC1>
__global__ __launch_bounds__(256, 2)
void moe_gemm_hmma_kernel(const float* __restrict__ bias) {
    constexpr int Kd = FC1 ? DD : HH;
    constexpr int Nd = FC1 ? HH : DD;
    constexpr int NCHUNK = Kd / 32;
    constexpr int NTILES = Nd / 128;

    extern __shared__ char smem[];
    int* stile = (int*)(smem + NSTAGE * STAGE_BYTES);
    int* sfill = stile + 2;
    const int tid = threadIdx.x;
    const int wid = tid >> 5, lane = tid & 31;

    const __half* aP = FC1 ? g_x16 : g_h16;
    const __half* wB = FC1 ? g_w1t : g_w2t;
    int* ctr = FC1 ? &g_tile1 : &g_tile2;

    if (tid < EE) sfill[tid] = g_fill[tid];
    if (tid == 0) stile[0] = atomicAdd(ctr, 1);
    __syncthreads();

    int total = 0;
#pragma unroll
    for (int e = 0; e < EE; e++)
        total += ((sfill[e] + 127) >> 7) * NTILES;

    const int srow = tid >> 1;
    const int part = tid & 1;
    const uint32_t sb = smem_u32(smem);
    const uint32_t rowoff = srow * ROWB + part * 32;

    const int warpM = (wid >> 1) * 32;
    const int warpN = (wid & 1) * 64;
    const int g = lane >> 3, lr = lane & 7;
    const uint32_t aLaneOff = (uint32_t)(warpM + lr + ((g & 1) << 3)) * ROWB + ((g >> 1) << 4);
    const uint32_t bLaneOff = (uint32_t)(warpN + lr + ((g >> 1) << 3)) * ROWB + ((g & 1) << 4);
    const int rr = lane >> 2;
    const int cc2 = (lane & 3) * 2;

    auto decode = [&](int t, int& e, int& cnt, int& m0, int& n0) {
        int rem = t; e = 0;
#pragma unroll 1
        for (; e < EE - 1; e++) {
            int te = ((sfill[e] + 127) >> 7) * NTILES;
            if (rem < te) break;
            rem -= te;
        }
        cnt = sfill[e];
        m0 = (rem / NTILES) * 128;
        n0 = (rem % NTILES) * 128;
    };

    auto mkptrs = [&](int e, int cnt, int m0, int n0,
                      const __half*& pah, const __half*& pbh, uint32_t& aok) {
        int m = m0 + srow;
        long long arow = -1;
        if (m < cnt) arow = FC1 ? (long long)g_perm[e * CAP + m] * DD
                                : (long long)(e * CAP + m) * HH;
        aok = (arow >= 0) ? 16u : 0u;
        pah = aP + (arow >= 0 ? arow : 0);
        pbh = wB + ((size_t)e * Nd + n0 + srow) * Kd;
    };

    auto stage = [&](const __half* pah, const __half* pbh, uint32_t aok, int c) {
        const uint32_t so = (uint32_t)(c % NSTAGE) * STAGE_BYTES + rowoff;
        const int k0 = c * 32 + part * 16;
#pragma unroll
        for (int i = 0; i < 2; i++) {
            int ke = k0 + i * 8;
            cp16(sb + so             + i * 16, pah + ke, aok);
            cp16(sb + so + ARR_BYTES + i * 16, pbh + ke, 16u);
        }
        CP_COMMIT();
    };

    int t_cur = stile[0];
    if (t_cur >= total) return;
    int ce, ccnt, cm0, cn0;
    decode(t_cur, ce, ccnt, cm0, cn0);
    const __half *c_pah, *c_pbh; uint32_t c_aok;
    mkptrs(ce, ccnt, cm0, cn0, c_pah, c_pbh, c_aok);

    if (tid == 0) stile[1] = atomicAdd(ctr, 1);
    int pp = 1;

    stage(c_pah, c_pbh, c_aok, 0);
    stage(c_pah, c_pbh, c_aok, 1);
    stage(c_pah, c_pbh, c_aok, 2);
    stage(c_pah, c_pbh, c_aok, 3);

    float acc[2][8][4];
#pragma unroll
    for (int i = 0; i < 2; i++)
#pragma unroll
        for (int j = 0; j < 8; j++)
#pragma unroll
            for (int k = 0; k < 4; k++) acc[i][j][k] = 0.f;

#pragma unroll 1
    while (true) {
#pragma unroll 1
        for (int c = 0; c < NCHUNK; c++) {
            if (c + 3 < NCHUNK)      asm volatile("cp.async.wait_group 3;" ::: "memory");
            else if (c + 2 < NCHUNK) asm volatile("cp.async.wait_group 2;" ::: "memory");
            else if (c + 1 < NCHUNK) asm volatile("cp.async.wait_group 1;" ::: "memory");
            else                     asm volatile("cp.async.wait_group 0;" ::: "memory");
            __syncthreads();
            if (c + 4 < NCHUNK) stage(c_pah, c_pbh, c_aok, c + 4);

            const uint32_t st = (uint32_t)(c % NSTAGE) * STAGE_BYTES;
            const uint32_t sA = sb + st;
            const uint32_t sB = sA + ARR_BYTES;
#pragma unroll
            for (int ks = 0; ks < 2; ks++) {
                const uint32_t ko = ks * 32;
                uint32_t bh[16];
#pragma unroll
                for (int tt = 0; tt < 4; tt++)
                    ldsm_x4(bh + 4 * tt, sB + ko + bLaneOff + tt * 16 * ROWB);
                uint32_t ah[8];
#pragma unroll
                for (int mt = 0; mt < 2; mt++)
                    ldsm_x4(ah + 4 * mt, sA + ko + aLaneOff + mt * 16 * ROWB);
#pragma unroll
                for (int mt = 0; mt < 2; mt++) {
#pragma unroll
                    for (int nf = 0; nf < 8; nf++) {
                        const uint32_t* B = &bh[4 * (nf >> 1) + 2 * (nf & 1)];
                        mma16816(acc[mt][nf], ah + 4 * mt, B);
                    }
                }
            }
        }

        __syncthreads();
        int t_next = stile[pp];
        bool v_next = (t_next < total);
        int ne = 0, ncnt = 0, nm0 = 0, nn0 = 0;
        const __half *n_pah = aP, *n_pbh = wB; uint32_t n_aok = 0;
        if (v_next) {
            decode(t_next, ne, ncnt, nm0, nn0);
            mkptrs(ne, ncnt, nm0, nn0, n_pah, n_pbh, n_aok);
            stage(n_pah, n_pbh, n_aok, 0);
            stage(n_pah, n_pbh, n_aok, 1);
            stage(n_pah, n_pbh, n_aok, 2);
            stage(n_pah, n_pbh, n_aok, 3);
        }
        if (tid == 0) stile[pp ^ 1] = atomicAdd(ctr, 1);
        pp ^= 1;

        {
            const int off = ce * CAP;
#pragma unroll
            for (int mt = 0; mt < 2; mt++) {
#pragma unroll
                for (int nf = 0; nf < 8; nf++) {
                    int col = cn0 + warpN + nf * 8 + cc2;
                    float bv0 = __ldg(&bias[(size_t)ce * Nd + col]);
                    float bv1 = __ldg(&bias[(size_t)ce * Nd + col + 1]);
#pragma unroll
                    for (int h = 0; h < 2; h++) {
                        int m = cm0 + warpM + mt * 16 + rr + h * 8;
                        if (m < ccnt) {
                            float v0 = acc[mt][nf][h * 2 + 0] + bv0;
                            float v1 = acc[mt][nf][h * 2 + 1] + bv1;
                            size_t orow = (size_t)(off + m);
                            if (FC1) {
                                v0 = fmaxf(v0, 0.f); v1 = fmaxf(v1, 0.f);
                                *(__half2*)(g_h16 + orow * HH + col) =
                                    __halves2half2(__float2half_rn(v0), __float2half_rn(v1));
                            } else {
                                *(float2*)(g_y + orow * DD + col) = make_float2(v0, v1);
                            }
                        }
                    }
                }
            }
        }
#pragma unroll
        for (int i = 0; i < 2; i++)
#pragma unroll
            for (int j = 0; j < 8; j++)
#pragma unroll
                for (int k = 0; k < 4; k++) acc[i][j][k] = 0.f;

        if (!v_next) break;
        ce = ne; ccnt = ncnt; cm0 = nm0; cn0 = nn0;
        c_pah = n_pah; c_pbh = n_pbh; c_aok = n_aok;
    }
}

// ---------------- combine + tail in one launch ----------------
// blocks [0, NT): combine token b.  blocks [NT, ...): zero tail of out.
__global__ __launch_bounds__(128)
void combine_kernel(float* __restrict__ out, long long total_out) {
    int b = blockIdx.x;
    if (b < NT) {
        int d = threadIdx.x * 4;
        int r0 = g_rowOf[2 * b + 0];
        int r1 = g_rowOf[2 * b + 1];
        float g0 = g_gate2[2 * b + 0];
        float g1 = g_gate2[2 * b + 1];
        float4 y0 = *(const float4*)&g_y[(size_t)r0 * DD + d];
        float4 y1 = *(const float4*)&g_y[(size_t)r1 * DD + d];
        float4 o;
        o.x = g0 * y0.x + g1 * y1.x;
        o.y = g0 * y0.y + g1 * y1.y;
        o.z = g0 * y0.z + g1 * y1.z;
        o.w = g0 * y0.w + g1 * y1.w;
        *(float4*)&out[(size_t)b * DD + d] = o;
    } else {
        long long start = (long long)NT * DD;
        long long i = start + (long long)(b - NT) * 128 + threadIdx.x;
        if (i < total_out) out[i] = 0.f;
    }
}

extern "C" void kernel_launch(void* const* d_in, const int* in_sizes, int n_in,
                              void* d_out, int out_size) {
    const float* x  = (const float*)d_in[0];
    const float* Wr = (const float*)d_in[1];
    const float* W1 = (const float*)d_in[2];
    const float* b1 = (const float*)d_in[3];
    const float* W2 = (const float*)d_in[4];
    const float* b2 = (const float*)d_in[5];
    float* out = (float*)d_out;

    cudaFuncSetAttribute(moe_gemm_hmma_kernel<true>,
                         cudaFuncAttributeMaxDynamicSharedMemorySize, SMEM_GEMM_BYTES);
    cudaFuncSetAttribute(moe_gemm_hmma_kernel<false>,
                         cudaFuncAttributeMaxDynamicSharedMemorySize, SMEM_GEMM_BYTES);

    setup_kernel<<<NB_SETUP, 256>>>(x, Wr, W1, W2);
    moe_gemm_hmma_kernel<true ><<<NPERSIST, 256, SMEM_GEMM_BYTES>>>(b1);
    moe_gemm_hmma_kernel<false><<<NPERSIST, 256, SMEM_GEMM_BYTES>>>(b2);

    long long main_elems = (long long)NT * DD;
    long long total = (long long)out_size;
    int tail_blocks = 0;
    if (total > main_elems)
        tail_blocks = (int)((total - main_elems + 127) / 128);
    combine_kernel<<<NT + tail_blocks, 128>>>(out, total);
}